// round 1
// baseline (speedup 1.0000x reference)
#include <cuda_runtime.h>
#include <math.h>

#define NB 8
#define NWAY 16
#define NBASE 8000
#define FEAT 512
#define SEM 300
#define SEMP 304            // SEM padded to /16 for the fused score GEMM
#define CAT 816             // FEAT + SEMP
#define NROW (NB*NWAY)      // 128
#define INV_TEMP 0.04419417382415922f  // 1/sqrt(512)

// ---------------- scratch (__device__ globals; no runtime allocation) ----------------
__device__ float g_H[(size_t)NB*NBASE*SEMP];     // leaky(base_seman@w1+b1), padded cols zeroed
__device__ float g_partBW[NB*16*FEAT];
__device__ float g_partH[NB*16*SEM];
__device__ float g_gatevis[NB*FEAT];
__device__ float g_gatesem[NB*SEM];
__device__ float g_qtot[NROW*FEAT];
__device__ float g_Qcat[NROW*CAT];               // [qkvg(512) | qh(300) | pad0(4)]
__device__ float g_c[NROW];
__device__ float g_m[NROW];
__device__ float g_Z[NROW];
__device__ float g_Wvc[FEAT*FEAT];               // w_vs @ fc_w
__device__ float g_part[(size_t)NB*32*NWAY*FEAT];

// ---------------- K1: partial column sums of base_weights (for mean) ----------------
__global__ void k1_partBW(const float* __restrict__ bw) {
    int b = blockIdx.y, s = blockIdx.x, t = threadIdx.x;
    int n0 = s * 500;
    const float* base = bw + ((size_t)(b*NBASE + n0))*FEAT;
    float a0 = 0.f, a1 = 0.f;
    for (int n = 0; n < 500; n++) {
        const float* r = base + (size_t)n*FEAT;
        a0 += r[t]; a1 += r[t+256];
    }
    g_partBW[(b*16+s)*FEAT + t]       = a0;
    g_partBW[(b*16+s)*FEAT + t + 256] = a1;
}

// ---------------- K2: H = leaky_relu(base_seman @ w1 + b1)  (64000x300 @ 300x300) ----
// BM=BN=64, BK=16, 256 threads, 4x4 microtile, smem A transposed.
__global__ void k2_hgemm(const float* __restrict__ A, const float* __restrict__ W1,
                         const float* __restrict__ B1) {
    __shared__ __align__(16) float As[16][68];
    __shared__ __align__(16) float Bs[16][68];
    int row0 = blockIdx.x * 64;
    int col0 = blockIdx.y * 64;
    int t = threadIdx.x;
    int tx = t & 15, ty = t >> 4;
    float acc[4][4] = {};
    for (int kt = 0; kt < 19; kt++) {
        { // A tile -> As[k][row]
            int kg = t & 3, row = t >> 2;
            int k0 = kt*16 + kg*4;
            const float* ap = A + (size_t)(row0 + row)*SEM + k0;
            float v0=0.f,v1=0.f,v2=0.f,v3=0.f;
            if (k0 + 3 < SEM) { float4 f = *reinterpret_cast<const float4*>(ap); v0=f.x;v1=f.y;v2=f.z;v3=f.w; }
            else {
                if (k0   < SEM) v0 = ap[0];
                if (k0+1 < SEM) v1 = ap[1];
                if (k0+2 < SEM) v2 = ap[2];
                if (k0+3 < SEM) v3 = ap[3];
            }
            As[kg*4+0][row]=v0; As[kg*4+1][row]=v1; As[kg*4+2][row]=v2; As[kg*4+3][row]=v3;
        }
        { // B tile -> Bs[k][n]
            int kk = t >> 4, n4 = (t & 15)*4;
            int k = kt*16 + kk, c = col0 + n4;
            float v0=0.f,v1=0.f,v2=0.f,v3=0.f;
            if (k < SEM) {
                const float* bp = W1 + (size_t)k*SEM + c;
                if (c + 3 < SEM) { float4 f = *reinterpret_cast<const float4*>(bp); v0=f.x;v1=f.y;v2=f.z;v3=f.w; }
                else {
                    if (c   < SEM) v0 = bp[0];
                    if (c+1 < SEM) v1 = bp[1];
                    if (c+2 < SEM) v2 = bp[2];
                    if (c+3 < SEM) v3 = bp[3];
                }
            }
            Bs[kk][n4+0]=v0; Bs[kk][n4+1]=v1; Bs[kk][n4+2]=v2; Bs[kk][n4+3]=v3;
        }
        __syncthreads();
        #pragma unroll
        for (int k = 0; k < 16; k++) {
            float4 af = *reinterpret_cast<const float4*>(&As[k][ty*4]);
            float4 bf = *reinterpret_cast<const float4*>(&Bs[k][tx*4]);
            float a[4] = {af.x, af.y, af.z, af.w};
            float bb[4] = {bf.x, bf.y, bf.z, bf.w};
            #pragma unroll
            for (int i = 0; i < 4; i++)
                #pragma unroll
                for (int j = 0; j < 4; j++) acc[i][j] += a[i]*bb[j];
        }
        __syncthreads();
    }
    #pragma unroll
    for (int i = 0; i < 4; i++) {
        int row = row0 + ty*4 + i;
        #pragma unroll
        for (int j = 0; j < 4; j++) {
            int col = col0 + tx*4 + j;
            if (col < SEMP) {
                float v = 0.f;
                if (col < SEM) {
                    float x = acc[i][j] + B1[col];
                    v = (x >= 0.f) ? x : 0.1f*x;
                }
                g_H[(size_t)row*SEMP + col] = v;
            }
        }
    }
}

// ---------------- K2b: partial column sums of H (for mean of calibrated sem) --------
__global__ void k2b_partH() {
    int b = blockIdx.y, s = blockIdx.x, t = threadIdx.x;
    if (t >= SEM) return;
    int n0 = s * 500;
    const float* base = g_H + ((size_t)(b*NBASE + n0))*SEMP;
    float a = 0.f;
    for (int n = 0; n < 500; n++) a += base[(size_t)n*SEMP + t];
    g_partH[(b*16+s)*SEM + t] = a;
}

// ---------------- K3: support semantic calibration + q_tot ---------------------------
__global__ void k3_qtot(const float* __restrict__ sf, const float* __restrict__ ss,
                        const float* __restrict__ W1, const float* __restrict__ B1,
                        const float* __restrict__ W2, const float* __restrict__ B2,
                        const float* __restrict__ Wq, const float* __restrict__ Wqs) {
    __shared__ float s_ss[SEM], s_hid[SEM], s_cal[SEM], s_sf[FEAT];
    int idx = blockIdx.x, t = threadIdx.x;
    if (t < SEM) s_ss[t] = ss[(size_t)idx*SEM + t];
    s_sf[t] = sf[(size_t)idx*FEAT + t];
    __syncthreads();
    if (t < SEM) {
        float h = B1[t];
        #pragma unroll 4
        for (int k = 0; k < SEM; k++) h += s_ss[k]*W1[(size_t)k*SEM + t];
        s_hid[t] = (h >= 0.f) ? h : 0.1f*h;
    }
    __syncthreads();
    if (t < SEM) {
        float c = B2[t];
        #pragma unroll 4
        for (int k = 0; k < SEM; k++) c += s_hid[k]*W2[(size_t)k*SEM + t];
        s_cal[t] = c;
    }
    __syncthreads();
    float q = 0.f;
    #pragma unroll 4
    for (int k = 0; k < FEAT; k++) q += s_sf[k]*Wq[(size_t)k*FEAT + t];
    #pragma unroll 4
    for (int k = 0; k < SEM; k++)  q += s_cal[k]*Wqs[(size_t)k*FEAT + t];
    g_qtot[(size_t)idx*FEAT + t] = q;
}

// ---------------- K4: means -> fusion gates ------------------------------------------
__global__ void k4_gates(const float* __restrict__ W2, const float* __restrict__ B2,
                         const float* __restrict__ Vw, const float* __restrict__ Vb,
                         const float* __restrict__ Sw, const float* __restrict__ Sb) {
    __shared__ float s_avg[FEAT + SEM];
    __shared__ float s_mh[SEM];
    int b = blockIdx.x, t = threadIdx.x;
    if (t < FEAT) {
        float a = 0.f;
        for (int s = 0; s < 16; s++) a += g_partBW[(b*16+s)*FEAT + t];
        s_avg[t] = a * (1.f/NBASE);
    }
    if (t < SEM) {
        float a = 0.f;
        for (int s = 0; s < 16; s++) a += g_partH[(b*16+s)*SEM + t];
        s_mh[t] = a * (1.f/NBASE);
    }
    __syncthreads();
    if (t < SEM) {
        float c = B2[t];
        #pragma unroll 4
        for (int k = 0; k < SEM; k++) c += s_mh[k]*W2[(size_t)k*SEM + t];
        s_avg[FEAT + t] = c;
    }
    __syncthreads();
    {
        float g = Vb[t];
        #pragma unroll 4
        for (int k = 0; k < FEAT+SEM; k++) g += s_avg[k]*Vw[(size_t)k*FEAT + t];
        g_gatevis[b*FEAT + t] = 1.f + 1.f/(1.f + expf(-g));
    }
    if (t < SEM) {
        float g = Sb[t];
        #pragma unroll 4
        for (int k = 0; k < FEAT+SEM; k++) g += s_avg[k]*Sw[(size_t)k*SEM + t];
        g_gatesem[b*SEM + t] = 1.f + 1.f/(1.f + expf(-g));
    }
}

// ---------------- K4b: Wvc = w_vs @ fc_w ---------------------------------------------
__global__ void k4b_wvc(const float* __restrict__ Wv, const float* __restrict__ Fc) {
    __shared__ float s_row[FEAT];
    int r = blockIdx.x, t = threadIdx.x;
    s_row[t] = Wv[(size_t)r*FEAT + t];
    __syncthreads();
    float acc = 0.f;
    #pragma unroll 4
    for (int k = 0; k < FEAT; k++) acc += s_row[k]*Fc[(size_t)k*FEAT + t];
    g_Wvc[(size_t)r*FEAT + t] = acc;
}

// ---------------- K5: fold W_k / gates / W2 into the query side ----------------------
__global__ void k5_qcat(const float* __restrict__ Wk, const float* __restrict__ Wks,
                        const float* __restrict__ W2, const float* __restrict__ B2) {
    __shared__ float s_q[FEAT];
    __shared__ float s_qsg[SEM];
    int idx = blockIdx.x, b = idx >> 4;
    int t = threadIdx.x, lane = t & 31, warp = t >> 5;   // 16 warps
    s_q[t] = g_qtot[(size_t)idx*FEAT + t];
    __syncthreads();
    // qkvg[d] = gate_vis[d] * sum_o q[o]*Wk[d][o]
    for (int i = 0; i < 32; i++) {
        int d = warp + i*16;
        float acc = 0.f;
        for (int o = lane; o < FEAT; o += 32) acc += s_q[o]*Wk[(size_t)d*FEAT + o];
        for (int off = 16; off; off >>= 1) acc += __shfl_xor_sync(0xffffffffu, acc, off);
        if (lane == 0) g_Qcat[(size_t)idx*CAT + d] = acc * g_gatevis[b*FEAT + d];
    }
    // qsg[s] = gate_sem[s] * sum_o q[o]*Wks[s][o]
    for (int i = 0; i < 19; i++) {
        int s = warp + i*16;
        if (s < SEM) {
            float acc = 0.f;
            for (int o = lane; o < FEAT; o += 32) acc += s_q[o]*Wks[(size_t)s*FEAT + o];
            for (int off = 16; off; off >>= 1) acc += __shfl_xor_sync(0xffffffffu, acc, off);
            if (lane == 0) s_qsg[s] = acc * g_gatesem[b*SEM + s];
        }
    }
    __syncthreads();
    // qh[s'] = sum_s qsg[s]*W2[s'][s]   (pad 300..303 with 0)
    for (int i = 0; i < 19; i++) {
        int sp = warp + i*16;
        if (sp < SEMP) {
            float acc = 0.f;
            if (sp < SEM) {
                for (int s = lane; s < SEM; s += 32) acc += s_qsg[s]*W2[(size_t)sp*SEM + s];
                for (int off = 16; off; off >>= 1) acc += __shfl_xor_sync(0xffffffffu, acc, off);
            }
            if (lane == 0) g_Qcat[(size_t)idx*CAT + FEAT + sp] = (sp < SEM) ? acc : 0.f;
        }
    }
    // constant term qsg . b2
    if (warp == 0) {
        float acc = 0.f;
        for (int s = lane; s < SEM; s += 32) acc += s_qsg[s]*B2[s];
        for (int off = 16; off; off >>= 1) acc += __shfl_xor_sync(0xffffffffu, acc, off);
        if (lane == 0) g_c[idx] = acc;
    }
}

// ---------------- K6: scores = Qcat @ [BW | H]^T / TEMP ------------------------------
// Per block: one episode b, a 128-wide n chunk, all 16 w. K=816 streamed in 16-tiles.
__global__ void k6_score(const float* __restrict__ bw, float* __restrict__ attn) {
    __shared__ __align__(16) float Qs[16][16];
    __shared__ __align__(16) float Xst[16][132];   // [k][n], padded stride
    int b = blockIdx.y, ch = blockIdx.x;
    int n0 = ch*128;
    int nvalid = NBASE - n0; if (nvalid > 128) nvalid = 128;
    int t = threadIdx.x, lane = t & 31, warp = t >> 5;  // 8 warps
    float acc0[4] = {0,0,0,0}, acc1[4] = {0,0,0,0};
    for (int kt = 0; kt < 51; kt++) {
        { // Q tile 16x16
            int w = t >> 4, k = t & 15;
            Qs[w][k] = g_Qcat[(size_t)(b*NWAY + w)*CAT + kt*16 + k];
        }
        #pragma unroll
        for (int i = 0; i < 2; i++) {  // X tile 128n x 16k, transposed into smem
            int v = t + 256*i;
            int kg = v & 3, n = v >> 2;
            int kk = kt*16 + kg*4;
            float4 f = make_float4(0.f,0.f,0.f,0.f);
            if (n < nvalid) {
                if (kk < FEAT)
                    f = *reinterpret_cast<const float4*>(bw + (size_t)(b*NBASE + n0 + n)*FEAT + kk);
                else
                    f = *reinterpret_cast<const float4*>(g_H + (size_t)(b*NBASE + n0 + n)*SEMP + (kk - FEAT));
            }
            Xst[kg*4+0][n] = f.x; Xst[kg*4+1][n] = f.y; Xst[kg*4+2][n] = f.z; Xst[kg*4+3][n] = f.w;
        }
        __syncthreads();
        #pragma unroll
        for (int k = 0; k < 16; k++) {
            float q0 = Qs[warp][k];
            float q1 = Qs[warp+8][k];
            float4 x = *reinterpret_cast<const float4*>(&Xst[k][lane*4]);
            acc0[0] += q0*x.x; acc0[1] += q0*x.y; acc0[2] += q0*x.z; acc0[3] += q0*x.w;
            acc1[0] += q1*x.x; acc1[1] += q1*x.y; acc1[2] += q1*x.z; acc1[3] += q1*x.w;
        }
        __syncthreads();
    }
    float c0 = g_c[b*NWAY + warp], c1 = g_c[b*NWAY + warp + 8];
    #pragma unroll
    for (int j = 0; j < 4; j++) {
        int n = lane*4 + j;
        if (n < nvalid) {
            attn[(size_t)(b*NWAY + warp    )*NBASE + n0 + n] = (acc0[j] + c0) * INV_TEMP;
            attn[(size_t)(b*NWAY + warp + 8)*NBASE + n0 + n] = (acc1[j] + c1) * INV_TEMP;
        }
    }
}

// ---------------- K7: softmax stats per (b,w) row ------------------------------------
__global__ void k7_stats(const float* __restrict__ attn) {
    __shared__ float red[256];
    int idx = blockIdx.x, t = threadIdx.x;
    const float* row = attn + (size_t)idx*NBASE;
    float m = -1e30f;
    for (int n = t; n < NBASE; n += 256) m = fmaxf(m, row[n]);
    red[t] = m; __syncthreads();
    for (int s = 128; s; s >>= 1) { if (t < s) red[t] = fmaxf(red[t], red[t+s]); __syncthreads(); }
    m = red[0]; __syncthreads();
    float z = 0.f;
    for (int n = t; n < NBASE; n += 256) z += expf(row[n] - m);
    red[t] = z; __syncthreads();
    for (int s = 128; s; s >>= 1) { if (t < s) red[t] += red[t+s]; __syncthreads(); }
    if (t == 0) { g_m[idx] = m; g_Z[idx] = red[0]; }
}

// ---------------- K8: partial attn @ base_weights ------------------------------------
__global__ void k8_part(const float* __restrict__ bw, const float* __restrict__ attn) {
    __shared__ float p[NWAY*250];
    int b = blockIdx.y, c = blockIdx.x, t = threadIdx.x;
    int n0 = c*250;
    for (int v = t; v < NWAY*250; v += 256) {
        int w = v/250, n = v%250;
        float s = attn[(size_t)(b*NWAY+w)*NBASE + n0 + n];
        p[w*250+n] = expf(s - g_m[b*NWAY+w]);
    }
    __syncthreads();
    float a0[NWAY], a1[NWAY];
    #pragma unroll
    for (int w = 0; w < NWAY; w++) { a0[w] = 0.f; a1[w] = 0.f; }
    for (int n = 0; n < 250; n++) {
        const float* r = bw + (size_t)(b*NBASE + n0 + n)*FEAT;
        float x0 = r[t], x1 = r[t+256];
        #pragma unroll
        for (int w = 0; w < NWAY; w++) {
            float pw = p[w*250+n];
            a0[w] += pw*x0; a1[w] += pw*x1;
        }
    }
    for (int w = 0; w < NWAY; w++) {
        size_t o = (size_t)((b*32 + c)*NWAY + w)*FEAT;
        g_part[o + t]       = a0[w];
        g_part[o + t + 256] = a1[w];
    }
}

// ---------------- K9: reduce partials, @Wvc, +residual -------------------------------
__global__ void k9_out(const float* __restrict__ sf, float* __restrict__ out) {
    __shared__ float s_s[FEAT];
    int idx = blockIdx.x, t = threadIdx.x;
    int b = idx >> 4, w = idx & 15;
    float acc = 0.f;
    for (int c = 0; c < 32; c++) acc += g_part[(size_t)((b*32+c)*NWAY + w)*FEAT + t];
    s_s[t] = acc / g_Z[idx];
    __syncthreads();
    float v = sf[(size_t)idx*FEAT + t];
    #pragma unroll 4
    for (int d = 0; d < FEAT; d++) v += s_s[d]*g_Wvc[(size_t)d*FEAT + t];
    out[(size_t)idx*FEAT + t] = v;
}

// ---------------- launch --------------------------------------------------------------
extern "C" void kernel_launch(void* const* d_in, const int* in_sizes, int n_in,
                              void* d_out, int out_size) {
    const float* sf  = (const float*)d_in[0];   // support_feat
    const float* bw  = (const float*)d_in[1];   // base_weights
    const float* ss  = (const float*)d_in[2];   // support_seman
    const float* bs  = (const float*)d_in[3];   // base_seman
    const float* w1  = (const float*)d_in[4];
    const float* b1  = (const float*)d_in[5];
    const float* w2  = (const float*)d_in[6];
    const float* b2  = (const float*)d_in[7];
    const float* vw  = (const float*)d_in[8];
    const float* vb  = (const float*)d_in[9];
    const float* swf = (const float*)d_in[10];
    const float* sb  = (const float*)d_in[11];
    const float* wq  = (const float*)d_in[12];
    const float* wk  = (const float*)d_in[13];
    const float* wv  = (const float*)d_in[14];
    const float* wqs = (const float*)d_in[15];
    const float* wks = (const float*)d_in[16];
    const float* fc  = (const float*)d_in[17];
    float* out  = (float*)d_out;
    float* attn = out + (size_t)NROW*FEAT;      // (out, attn_score) concatenated

    k1_partBW<<<dim3(16, NB), 256>>>(bw);
    k2_hgemm <<<dim3(1000, 5), 256>>>(bs, w1, b1);
    k2b_partH<<<dim3(16, NB), 320>>>();
    k3_qtot  <<<NROW, 512>>>(sf, ss, w1, b1, w2, b2, wq, wqs);
    k4_gates <<<NB, 512>>>(w2, b2, vw, vb, swf, sb);
    k4b_wvc  <<<FEAT, 512>>>(wv, fc);
    k5_qcat  <<<NROW, 512>>>(wk, wks, w2, b2);
    k6_score <<<dim3(63, NB), 256>>>(bw, attn);
    k7_stats <<<NROW, 256>>>(attn);
    k8_part  <<<dim3(32, NB), 256>>>(bw, attn);
    k9_out   <<<NROW, 512>>>(sf, out);
}